// round 10
// baseline (speedup 1.0000x reference)
#include <cuda_runtime.h>
#include <math.h>
#include <stdint.h>

#define BB 2
#define SS 2048
#define HH 1024
#define FF 2816
#define EE 8
#define KK 2
#define TT (BB*SS)
#define SLOTS (TT*KK)
#define BM 128
#define PADMAX (SLOTS + EE*BM)    // 9216
#define RT_MAX (PADMAX/BM)        // 72

__device__ float g_h1[(size_t)PADMAX * FF];
__device__ float g_y [(size_t)PADMAX * HH];
__device__ int   g_count[EE];
__device__ int   g_fill[EE];
__device__ float g_psum[EE];
__device__ int   g_base[EE+1];
__device__ int   g_sorted_token[PADMAX];
__device__ int   g_slot_row[SLOTS];
__device__ int   g_tok_e[SLOTS];
__device__ float g_tok_w[SLOTS];

__device__ __forceinline__ uint32_t to_tf32(float x) {
    uint32_t r; asm("cvt.rna.tf32.f32 %0, %1;" : "=r"(r) : "f"(x)); return r;
}
__device__ __forceinline__ uint2 sp2(float x) {
    uint2 r;
    r.x = to_tf32(x);
    r.y = to_tf32(x - __uint_as_float(r.x));
    return r;
}
__device__ __forceinline__ void mma_tf32(float* d, const uint32_t* a, uint32_t b0, uint32_t b1) {
    asm volatile("mma.sync.aligned.m16n8k8.row.col.f32.tf32.tf32.f32 "
                 "{%0,%1,%2,%3}, {%4,%5,%6,%7}, {%8,%9}, {%0,%1,%2,%3};"
                 : "+f"(d[0]), "+f"(d[1]), "+f"(d[2]), "+f"(d[3])
                 : "r"(a[0]), "r"(a[1]), "r"(a[2]), "r"(a[3]), "r"(b0), "r"(b1));
}

__global__ void init_kernel() {
    int i = blockIdx.x * blockDim.x + threadIdx.x;
    if (i < PADMAX) g_sorted_token[i] = 0;
    if (i < EE) { g_count[i] = 0; g_fill[i] = 0; g_psum[i] = 0.f; }
}

__global__ void router_kernel(const float* __restrict__ x, const float* __restrict__ rw) {
    int t = blockIdx.x;
    __shared__ float sp[128][EE];
    float acc[EE];
#pragma unroll
    for (int e = 0; e < EE; e++) acc[e] = 0.f;
    const float* xt = x + (size_t)t * HH;
    for (int h = threadIdx.x; h < HH; h += 128) {
        float xv = xt[h];
#pragma unroll
        for (int e = 0; e < EE; e++) acc[e] += xv * rw[e*HH + h];
    }
#pragma unroll
    for (int e = 0; e < EE; e++) sp[threadIdx.x][e] = acc[e];
    __syncthreads();
    for (int s = 64; s > 0; s >>= 1) {
        if (threadIdx.x < s)
#pragma unroll
            for (int e = 0; e < EE; e++) sp[threadIdx.x][e] += sp[threadIdx.x + s][e];
        __syncthreads();
    }
    if (threadIdx.x == 0) {
        float lg[EE];
#pragma unroll
        for (int e = 0; e < EE; e++) lg[e] = sp[0][e];
        int i0 = 0;
#pragma unroll
        for (int e = 1; e < EE; e++) if (lg[e] > lg[i0]) i0 = e;
        int i1 = -1;
#pragma unroll
        for (int e = 0; e < EE; e++) {
            if (e == i0) continue;
            if (i1 < 0 || lg[e] > lg[i1]) i1 = e;
        }
        float ex = expf(lg[i1] - lg[i0]);
        g_tok_e[2*t] = i0;  g_tok_e[2*t+1] = i1;
        g_tok_w[2*t] = 1.f/(1.f+ex);  g_tok_w[2*t+1] = ex/(1.f+ex);
        atomicAdd(&g_count[i0], 1);
        atomicAdd(&g_count[i1], 1);
        float m = lg[0];
#pragma unroll
        for (int e = 1; e < EE; e++) m = fmaxf(m, lg[e]);
        float s = 0.f, pe[EE];
#pragma unroll
        for (int e = 0; e < EE; e++) { pe[e] = expf(lg[e] - m); s += pe[e]; }
        float inv = 1.f / s;
#pragma unroll
        for (int e = 0; e < EE; e++) atomicAdd(&g_psum[e], pe[e] * inv);
    }
}

__global__ void setup_kernel(float* __restrict__ out_aux) {
    if (threadIdx.x == 0) {
        int base = 0;
        for (int e = 0; e < EE; e++) {
            g_base[e] = base;
            base += (g_count[e] + BM - 1) & ~(BM - 1);
        }
        g_base[EE] = base;
        float aux = 0.f;
        for (int e = 0; e < EE; e++)
            aux += ((float)g_count[e] / SLOTS) * (g_psum[e] / TT);
        out_aux[0] = aux * EE;
    }
}

__global__ void scatter_kernel() {
    int s = blockIdx.x * blockDim.x + threadIdx.x;
    if (s >= SLOTS) return;
    int e = g_tok_e[s];
    int row = g_base[e] + atomicAdd(&g_fill[e], 1);
    g_sorted_token[row] = s >> 1;
    g_slot_row[s] = row;
}

// ==== GEMM1: h1 = silu(x@Wg)*(x@Wu). 128 thr, CTA 128M x 64F (interleaved 128 cols) ====
__global__ __launch_bounds__(128, 2) void gemm1_kernel(
    const float* __restrict__ x, const float* __restrict__ wg, const float* __restrict__ wu)
{
    int r0 = blockIdx.x * BM;
    if (r0 >= g_base[EE]) return;
    int n0f = blockIdx.y * 64;
    int e = 0;
    while (g_base[e+1] <= r0) e++;

    __shared__ __align__(16) uint2 As[2][8][132];
    __shared__ __align__(16) uint2 Bs[2][8][132];
    __shared__ int s_tok[128];

    int tid = threadIdx.x, lane = tid & 31, wid = tid >> 5;
    s_tok[tid] = g_sorted_token[r0 + tid];
    __syncthreads();

    int wm = (wid >> 1) * 64, wn = (wid & 1) * 64;
    int fr = lane >> 2, kq = lane & 3;
    int brw = tid >> 4, f4 = (tid & 15) * 4;

    const float* arow = x + (size_t)s_tok[tid] * HH;
    const float* grow = wg + (size_t)e * HH * FF + n0f + f4;
    const float* urow = wu + (size_t)e * HH * FF + n0f + f4;

    float d[4][8][4];
#pragma unroll
    for (int i = 0; i < 4; i++)
#pragma unroll
        for (int j = 0; j < 8; j++)
#pragma unroll
            for (int k = 0; k < 4; k++) d[i][j][k] = 0.f;

    // chunk 0 -> stage 0
    {
        float4 a0 = *(const float4*)(arow), a1 = *(const float4*)(arow + 4);
        float af[8] = {a0.x,a0.y,a0.z,a0.w,a1.x,a1.y,a1.z,a1.w};
#pragma unroll
        for (int j = 0; j < 8; j++) As[0][j][tid] = sp2(af[j]);
        float4 g = *(const float4*)(grow + (size_t)brw * FF);
        float4 u = *(const float4*)(urow + (size_t)brw * FF);
        float gf[4] = {g.x,g.y,g.z,g.w}, uf[4] = {u.x,u.y,u.z,u.w};
#pragma unroll
        for (int j = 0; j < 4; j++) {
            uint2 qg = sp2(gf[j]), qu = sp2(uf[j]);
            *(uint4*)&Bs[0][brw][2*(f4+j)] = make_uint4(qg.x, qg.y, qu.x, qu.y);
        }
    }
    float4 pa0 = *(const float4*)(arow + 8), pa1 = *(const float4*)(arow + 12);
    float4 pg = *(const float4*)(grow + (size_t)(8 + brw) * FF);
    float4 pu = *(const float4*)(urow + (size_t)(8 + brw) * FF);
    __syncthreads();

    const int chunks = HH / 8;   // 128
    for (int c = 0; c < chunks; c++) {
        int s = c & 1;
        if (c + 1 < chunks) {
            int s1 = s ^ 1;
            float af[8] = {pa0.x,pa0.y,pa0.z,pa0.w,pa1.x,pa1.y,pa1.z,pa1.w};
#pragma unroll
            for (int j = 0; j < 8; j++) As[s1][j][tid] = sp2(af[j]);
            float gf[4] = {pg.x,pg.y,pg.z,pg.w}, uf[4] = {pu.x,pu.y,pu.z,pu.w};
#pragma unroll
            for (int j = 0; j < 4; j++) {
                uint2 qg = sp2(gf[j]), qu = sp2(uf[j]);
                *(uint4*)&Bs[s1][brw][2*(f4+j)] = make_uint4(qg.x, qg.y, qu.x, qu.y);
            }
        }
        if (c + 2 < chunks) {
            pa0 = *(const float4*)(arow + (c+2)*8);
            pa1 = *(const float4*)(arow + (c+2)*8 + 4);
            pg = *(const float4*)(grow + (size_t)((c+2)*8 + brw) * FF);
            pu = *(const float4*)(urow + (size_t)((c+2)*8 + brw) * FF);
        }
        uint32_t ahi[4][4], alo[4][4];
#pragma unroll
        for (int mt = 0; mt < 4; mt++) {
            int mb = wm + mt*16 + fr;
            uint2 q0 = As[s][kq][mb],   q1 = As[s][kq][mb+8];
            uint2 q2 = As[s][kq+4][mb], q3 = As[s][kq+4][mb+8];
            ahi[mt][0]=q0.x; ahi[mt][1]=q1.x; ahi[mt][2]=q2.x; ahi[mt][3]=q3.x;
            alo[mt][0]=q0.y; alo[mt][1]=q1.y; alo[mt][2]=q2.y; alo[mt][3]=q3.y;
        }
#pragma unroll
        for (int nt = 0; nt < 8; nt++) {
            int nn = wn + nt*8 + fr;
            uint2 b0 = Bs[s][kq][nn], b1 = Bs[s][kq+4][nn];
#pragma unroll
            for (int mt = 0; mt < 4; mt++) {
                mma_tf32(d[mt][nt], ahi[mt], b0.x, b1.x);
                mma_tf32(d[mt][nt], ahi[mt], b0.y, b1.y);
                mma_tf32(d[mt][nt], alo[mt], b0.x, b1.x);
            }
        }
        __syncthreads();
    }

#pragma unroll
    for (int mt = 0; mt < 4; mt++) {
        int row = r0 + wm + mt*16 + fr;
#pragma unroll
        for (int nt = 0; nt < 8; nt++) {
            int f = n0f + (wn >> 1) + nt*4 + kq;
            float gv = d[mt][nt][0], uv = d[mt][nt][1];
            g_h1[(size_t)row * FF + f] = (gv / (1.f + expf(-gv))) * uv;
            gv = d[mt][nt][2]; uv = d[mt][nt][3];
            g_h1[(size_t)(row + 8) * FF + f] = (gv / (1.f + expf(-gv))) * uv;
        }
    }
}

// ==== GEMM2: y = h1 @ Wd. 128 thr, CTA 128M x 128N ====
__global__ __launch_bounds__(128, 2) void gemm2_kernel(const float* __restrict__ wd)
{
    int r0 = blockIdx.x * BM;
    if (r0 >= g_base[EE]) return;
    int n0 = blockIdx.y * 128;
    int e = 0;
    while (g_base[e+1] <= r0) e++;

    __shared__ __align__(16) uint2 As[2][8][132];
    __shared__ __align__(16) uint2 Bs[2][8][132];

    int tid = threadIdx.x, lane = tid & 31, wid = tid >> 5;
    int wm = (wid >> 1) * 64, wn = (wid & 1) * 64;
    int fr = lane >> 2, kq = lane & 3;
    int brw = tid >> 4, n8 = (tid & 15) * 8;

    const float* arow = g_h1 + (size_t)(r0 + tid) * FF;
    const float* brow = wd + (size_t)e * FF * HH + n0 + n8;

    float d[4][8][4];
#pragma unroll
    for (int i = 0; i < 4; i++)
#pragma unroll
        for (int j = 0; j < 8; j++)
#pragma unroll
            for (int k = 0; k < 4; k++) d[i][j][k] = 0.f;

    {
        float4 a0 = *(const float4*)(arow), a1 = *(const float4*)(arow + 4);
        float af[8] = {a0.x,a0.y,a0.z,a0.w,a1.x,a1.y,a1.z,a1.w};
#pragma unroll
        for (int j = 0; j < 8; j++) As[0][j][tid] = sp2(af[j]);
        float4 b0 = *(const float4*)(brow + (size_t)brw * HH);
        float4 b1 = *(const float4*)(brow + (size_t)brw * HH + 4);
        float bf[8] = {b0.x,b0.y,b0.z,b0.w,b1.x,b1.y,b1.z,b1.w};
#pragma unroll
        for (int j = 0; j < 4; j++) {
            uint2 q0 = sp2(bf[2*j]), q1 = sp2(bf[2*j+1]);
            *(uint4*)&Bs[0][brw][n8 + 2*j] = make_uint4(q0.x, q0.y, q1.x, q1.y);
        }
    }
    float4 pa0 = *(const float4*)(arow + 8), pa1 = *(const float4*)(arow + 12);
    float4 pb0 = *(const float4*)(brow + (size_t)(8 + brw) * HH);
    float4 pb1 = *(const float4*)(brow + (size_t)(8 + brw) * HH + 4);
    __syncthreads();

    const int chunks = FF / 8;   // 352
    for (int c = 0; c < chunks; c++) {
        int s = c & 1;
        if (c + 1 < chunks) {
            int s1 = s ^ 1;
            float af[8] = {pa0.x,pa0.y,pa0.z,pa0.w,pa1.x,pa1.y,pa1.z,pa1.w};
#pragma unroll
            for (int j = 0; j < 8; j++) As[s1][j][tid] = sp2(af[j]);
            float bf[8] = {pb0.x,pb0.y,pb0.z,pb0.w,pb1.x,pb1.y,pb1.z,pb1.w};
#pragma unroll
            for (int j = 0; j < 4; j++) {
                uint2 q0 = sp2(bf[2*j]), q1 = sp2(bf[2*j+1]);
                *(uint4*)&Bs[s1][brw][n8 + 2*j] = make_uint4(q0.x, q0.y, q1.x, q1.y);
            }
        }
        if (c + 2 < chunks) {
            pa0 = *(const float4*)(arow + (c+2)*8);
            pa1 = *(const float4*)(arow + (c+2)*8 + 4);
            pb0 = *(const float4*)(brow + (size_t)((c+2)*8 + brw) * HH);
            pb1 = *(const float4*)(brow + (size_t)((c+2)*8 + brw) * HH + 4);
        }
        uint32_t ahi[4][4], alo[4][4];
#pragma unroll
        for (int mt = 0; mt < 4; mt++) {
            int mb = wm + mt*16 + fr;
            uint2 q0 = As[s][kq][mb],   q1 = As[s][kq][mb+8];
            uint2 q2 = As[s][kq+4][mb], q3 = As[s][kq+4][mb+8];
            ahi[mt][0]=q0.x; ahi[mt][1]=q1.x; ahi[mt][2]=q2.x; ahi[mt][3]=q3.x;
            alo[mt][0]=q0.y; alo[mt][1]=q1.y; alo[mt][2]=q2.y; alo[mt][3]=q3.y;
        }
#pragma unroll
        for (int nt = 0; nt < 8; nt++) {
            int nn = wn + nt*8 + fr;
            uint2 b0 = Bs[s][kq][nn], b1 = Bs[s][kq+4][nn];
#pragma unroll
            for (int mt = 0; mt < 4; mt++) {
                mma_tf32(d[mt][nt], ahi[mt], b0.x, b1.x);
                mma_tf32(d[mt][nt], ahi[mt], b0.y, b1.y);
                mma_tf32(d[mt][nt], alo[mt], b0.x, b1.x);
            }
        }
        __syncthreads();
    }

#pragma unroll
    for (int mt = 0; mt < 4; mt++) {
        int row = r0 + wm + mt*16 + fr;
#pragma unroll
        for (int nt = 0; nt < 8; nt++) {
            int col = n0 + wn + nt*8 + 2*kq;
            *(float2*)&g_y[(size_t)row * HH + col]       = make_float2(d[mt][nt][0], d[mt][nt][1]);
            *(float2*)&g_y[(size_t)(row + 8) * HH + col] = make_float2(d[mt][nt][2], d[mt][nt][3]);
        }
    }
}

__global__ void combine_kernel(float* __restrict__ out) {
    int i = blockIdx.x * blockDim.x + threadIdx.x;
    if (i >= TT * (HH/4)) return;
    int t = i / (HH/4);
    int c = (i - t * (HH/4)) * 4;
    int r0 = g_slot_row[2*t], r1 = g_slot_row[2*t+1];
    float w0 = g_tok_w[2*t], w1 = g_tok_w[2*t+1];
    float4 y0 = *(const float4*)(g_y + (size_t)r0 * HH + c);
    float4 y1 = *(const float4*)(g_y + (size_t)r1 * HH + c);
    float4 o;
    o.x = w0*y0.x + w1*y1.x;  o.y = w0*y0.y + w1*y1.y;
    o.z = w0*y0.z + w1*y1.z;  o.w = w0*y0.w + w1*y1.w;
    *(float4*)(out + (size_t)t * HH + c) = o;
}

extern "C" void kernel_launch(void* const* d_in, const int* in_sizes, int n_in,
                              void* d_out, int out_size) {
    const float* x  = (const float*)d_in[0];
    const float* rw = (const float*)d_in[1];
    const float* wg = (const float*)d_in[2];
    const float* wu = (const float*)d_in[3];
    const float* wd = (const float*)d_in[4];
    float* out = (float*)d_out;

    init_kernel<<<(PADMAX + 255) / 256, 256>>>();
    router_kernel<<<TT, 128>>>(x, rw);
    setup_kernel<<<1, 32>>>(out + (size_t)TT * HH);
    scatter_kernel<<<(SLOTS + 255) / 256, 256>>>();
    gemm1_kernel<<<dim3(RT_MAX, FF/64), 128>>>(x, wg, wu);
    gemm2_kernel<<<dim3(RT_MAX, HH/128), 128>>>(wd);
    combine_kernel<<<(TT * (HH/4) + 255) / 256, 256>>>(out);
}

// round 11
// speedup vs baseline: 1.8017x; 1.8017x over previous
#include <cuda_runtime.h>
#include <cuda_bf16.h>
#include <math.h>
#include <stdint.h>

#define BB 2
#define SS 2048
#define HH 1024
#define FF 2816
#define EE 8
#define KK 2
#define TT (BB*SS)
#define SLOTS (TT*KK)
#define BM 128
#define PADMAX (SLOTS + EE*BM)    // 9216
#define RT_MAX (PADMAX/BM)        // 72
#define PIT 136                   // uint2 pitch; 2*PIT % 32 == 16 -> conflict-free frags

__device__ float g_h1[(size_t)PADMAX * FF];
__device__ float g_y [(size_t)PADMAX * HH];
__device__ int   g_count[EE];
__device__ int   g_fill[EE];
__device__ float g_psum[EE];
__device__ int   g_base[EE+1];
__device__ int   g_sorted_token[PADMAX];
__device__ int   g_slot_row[SLOTS];
__device__ int   g_tok_e[SLOTS];
__device__ float g_tok_w[SLOTS];

// pack two floats (k-even, k-odd) into (hi-pair, lo-pair) bf16x2 words
__device__ __forceinline__ uint2 spb(float x, float y) {
    __nv_bfloat16 hx = __float2bfloat16(x);
    __nv_bfloat16 hy = __float2bfloat16(y);
    __nv_bfloat16 lx = __float2bfloat16(x - __bfloat162float(hx));
    __nv_bfloat16 ly = __float2bfloat16(y - __bfloat162float(hy));
    uint2 r;
    r.x = (uint32_t)__bfloat16_as_ushort(hx) | ((uint32_t)__bfloat16_as_ushort(hy) << 16);
    r.y = (uint32_t)__bfloat16_as_ushort(lx) | ((uint32_t)__bfloat16_as_ushort(ly) << 16);
    return r;
}
__device__ __forceinline__ void mma_bf16(float* d, const uint32_t* a, uint32_t b0, uint32_t b1) {
    asm volatile("mma.sync.aligned.m16n8k16.row.col.f32.bf16.bf16.f32 "
                 "{%0,%1,%2,%3}, {%4,%5,%6,%7}, {%8,%9}, {%0,%1,%2,%3};"
                 : "+f"(d[0]), "+f"(d[1]), "+f"(d[2]), "+f"(d[3])
                 : "r"(a[0]), "r"(a[1]), "r"(a[2]), "r"(a[3]), "r"(b0), "r"(b1));
}

__global__ void init_kernel() {
    int i = blockIdx.x * blockDim.x + threadIdx.x;
    if (i < PADMAX) g_sorted_token[i] = 0;
    if (i < EE) { g_count[i] = 0; g_fill[i] = 0; g_psum[i] = 0.f; }
}

__global__ void router_kernel(const float* __restrict__ x, const float* __restrict__ rw) {
    int t = blockIdx.x;
    __shared__ float sp[128][EE];
    float acc[EE];
#pragma unroll
    for (int e = 0; e < EE; e++) acc[e] = 0.f;
    const float* xt = x + (size_t)t * HH;
    for (int h = threadIdx.x; h < HH; h += 128) {
        float xv = xt[h];
#pragma unroll
        for (int e = 0; e < EE; e++) acc[e] += xv * rw[e*HH + h];
    }
#pragma unroll
    for (int e = 0; e < EE; e++) sp[threadIdx.x][e] = acc[e];
    __syncthreads();
    for (int s = 64; s > 0; s >>= 1) {
        if (threadIdx.x < s)
#pragma unroll
            for (int e = 0; e < EE; e++) sp[threadIdx.x][e] += sp[threadIdx.x + s][e];
        __syncthreads();
    }
    if (threadIdx.x == 0) {
        float lg[EE];
#pragma unroll
        for (int e = 0; e < EE; e++) lg[e] = sp[0][e];
        int i0 = 0;
#pragma unroll
        for (int e = 1; e < EE; e++) if (lg[e] > lg[i0]) i0 = e;
        int i1 = -1;
#pragma unroll
        for (int e = 0; e < EE; e++) {
            if (e == i0) continue;
            if (i1 < 0 || lg[e] > lg[i1]) i1 = e;
        }
        float ex = expf(lg[i1] - lg[i0]);
        g_tok_e[2*t] = i0;  g_tok_e[2*t+1] = i1;
        g_tok_w[2*t] = 1.f/(1.f+ex);  g_tok_w[2*t+1] = ex/(1.f+ex);
        atomicAdd(&g_count[i0], 1);
        atomicAdd(&g_count[i1], 1);
        float m = lg[0];
#pragma unroll
        for (int e = 1; e < EE; e++) m = fmaxf(m, lg[e]);
        float s = 0.f, pe[EE];
#pragma unroll
        for (int e = 0; e < EE; e++) { pe[e] = expf(lg[e] - m); s += pe[e]; }
        float inv = 1.f / s;
#pragma unroll
        for (int e = 0; e < EE; e++) atomicAdd(&g_psum[e], pe[e] * inv);
    }
}

__global__ void setup_kernel(float* __restrict__ out_aux) {
    if (threadIdx.x == 0) {
        int base = 0;
        for (int e = 0; e < EE; e++) {
            g_base[e] = base;
            base += (g_count[e] + BM - 1) & ~(BM - 1);
        }
        g_base[EE] = base;
        float aux = 0.f;
        for (int e = 0; e < EE; e++)
            aux += ((float)g_count[e] / SLOTS) * (g_psum[e] / TT);
        out_aux[0] = aux * EE;
    }
}

__global__ void scatter_kernel() {
    int s = blockIdx.x * blockDim.x + threadIdx.x;
    if (s >= SLOTS) return;
    int e = g_tok_e[s];
    int row = g_base[e] + atomicAdd(&g_fill[e], 1);
    g_sorted_token[row] = s >> 1;
    g_slot_row[s] = row;
}

// ==== GEMM1: h1 = silu(x@Wg)*(x@Wu). 256 thr, CTA 128M x 64F (gate/up interleaved) ====
__global__ __launch_bounds__(256, 2) void gemm1_kernel(
    const float* __restrict__ x, const float* __restrict__ wg, const float* __restrict__ wu)
{
    int r0 = blockIdx.x * BM;
    if (r0 >= g_base[EE]) return;
    int n0f = blockIdx.y * 64;
    int e = 0;
    while (g_base[e+1] <= r0) e++;

    __shared__ __align__(16) uint2 As[2][8][PIT];
    __shared__ __align__(16) uint2 Bs[2][8][PIT];
    __shared__ int s_tok[128];

    int tid = threadIdx.x, lane = tid & 31, wid = tid >> 5;
    if (tid < 128) s_tok[tid] = g_sorted_token[r0 + tid];
    __syncthreads();

    int wm = (wid >> 1) * 32, wn = (wid & 1) * 64;
    int fr = lane >> 2, kq = lane & 3;

    // A loader: row = tid&127, khalf = tid>>7 -> pairs khalf*4 + j
    int a_row = tid & 127, a_kh = tid >> 7;
    const float* arow = x + (size_t)s_tok[a_row] * HH + a_kh * 8;
    // B loader: kp = tid>>5 (0..7), 2 features per lane
    int b_kp = tid >> 5, b_f = (tid & 31) * 2;
    const float* grow = wg + (size_t)e * HH * FF + n0f + b_f;
    const float* urow = wu + (size_t)e * HH * FF + n0f + b_f;

    float d[2][8][4];
#pragma unroll
    for (int i = 0; i < 2; i++)
#pragma unroll
        for (int j = 0; j < 8; j++)
#pragma unroll
            for (int k = 0; k < 4; k++) d[i][j][k] = 0.f;

#define G1_STS(st, A0, A1, G0, G1v, U0, U1v) do {                               \
    float af_[8] = {(A0).x,(A0).y,(A0).z,(A0).w,(A1).x,(A1).y,(A1).z,(A1).w};   \
    _Pragma("unroll")                                                           \
    for (int j_ = 0; j_ < 4; j_++)                                              \
        As[st][a_kh*4 + j_][a_row] = spb(af_[2*j_], af_[2*j_+1]);               \
    uint2 c0_ = spb((G0).x, (G1v).x);                                           \
    uint2 c1_ = spb((U0).x, (U1v).x);                                           \
    uint2 c2_ = spb((G0).y, (G1v).y);                                           \
    uint2 c3_ = spb((U0).y, (U1v).y);                                           \
    *(uint4*)&Bs[st][b_kp][2*b_f]     = make_uint4(c0_.x, c0_.y, c1_.x, c1_.y); \
    *(uint4*)&Bs[st][b_kp][2*b_f + 2] = make_uint4(c2_.x, c2_.y, c3_.x, c3_.y); \
} while (0)

    // chunk 0 direct
    {
        float4 a0 = *(const float4*)(arow), a1 = *(const float4*)(arow + 4);
        size_t k0 = (size_t)(2*b_kp) * FF;
        float2 g0 = *(const float2*)(grow + k0),      g1 = *(const float2*)(grow + k0 + FF);
        float2 u0 = *(const float2*)(urow + k0),      u1 = *(const float2*)(urow + k0 + FF);
        G1_STS(0, a0, a1, g0, g1, u0, u1);
    }
    // prefetch chunk 1
    float4 pa0 = *(const float4*)(arow + 16), pa1 = *(const float4*)(arow + 20);
    float2 pg0, pg1, pu0, pu1;
    {
        size_t k0 = (size_t)(16 + 2*b_kp) * FF;
        pg0 = *(const float2*)(grow + k0);  pg1 = *(const float2*)(grow + k0 + FF);
        pu0 = *(const float2*)(urow + k0);  pu1 = *(const float2*)(urow + k0 + FF);
    }
    __syncthreads();

    const int chunks = HH / 16;   // 64
    for (int c = 0; c < chunks; c++) {
        int s = c & 1;
        if (c + 1 < chunks) {
            int s1 = s ^ 1;
            G1_STS(s1, pa0, pa1, pg0, pg1, pu0, pu1);
        }
        if (c + 2 < chunks) {
            pa0 = *(const float4*)(arow + (c+2)*16);
            pa1 = *(const float4*)(arow + (c+2)*16 + 4);
            size_t k0 = (size_t)((c+2)*16 + 2*b_kp) * FF;
            pg0 = *(const float2*)(grow + k0);  pg1 = *(const float2*)(grow + k0 + FF);
            pu0 = *(const float2*)(urow + k0);  pu1 = *(const float2*)(urow + k0 + FF);
        }
        uint32_t ahi[2][4], alo[2][4];
#pragma unroll
        for (int mt = 0; mt < 2; mt++) {
            int mb = wm + mt*16 + fr;
            uint2 q0 = As[s][kq][mb],   q1 = As[s][kq][mb+8];
            uint2 q2 = As[s][kq+4][mb], q3 = As[s][kq+4][mb+8];
            ahi[mt][0]=q0.x; ahi[mt][1]=q1.x; ahi[mt][2]=q2.x; ahi[mt][3]=q3.x;
            alo[mt][0]=q0.y; alo[mt][1]=q1.y; alo[mt][2]=q2.y; alo[mt][3]=q3.y;
        }
#pragma unroll
        for (int nt = 0; nt < 8; nt++) {
            int nn = wn + nt*8 + fr;
            uint2 b0 = Bs[s][kq][nn], b1 = Bs[s][kq+4][nn];
#pragma unroll
            for (int mt = 0; mt < 2; mt++) {
                mma_bf16(d[mt][nt], ahi[mt], b0.x, b1.x);
                mma_bf16(d[mt][nt], ahi[mt], b0.y, b1.y);
                mma_bf16(d[mt][nt], alo[mt], b0.x, b1.x);
            }
        }
        __syncthreads();
    }
#undef G1_STS

#pragma unroll
    for (int mt = 0; mt < 2; mt++) {
        int row = r0 + wm + mt*16 + fr;
#pragma unroll
        for (int nt = 0; nt < 8; nt++) {
            int f = n0f + (wn >> 1) + nt*4 + kq;
            float gv = d[mt][nt][0], uv = d[mt][nt][1];
            g_h1[(size_t)row * FF + f] = (gv / (1.f + expf(-gv))) * uv;
            gv = d[mt][nt][2]; uv = d[mt][nt][3];
            g_h1[(size_t)(row + 8) * FF + f] = (gv / (1.f + expf(-gv))) * uv;
        }
    }
}

// ==== GEMM2: y = h1 @ Wd. 256 thr, CTA 128M x 128N ====
__global__ __launch_bounds__(256, 2) void gemm2_kernel(const float* __restrict__ wd)
{
    int r0 = blockIdx.x * BM;
    if (r0 >= g_base[EE]) return;
    int n0 = blockIdx.y * 128;
    int e = 0;
    while (g_base[e+1] <= r0) e++;

    __shared__ __align__(16) uint2 As[2][8][PIT];
    __shared__ __align__(16) uint2 Bs[2][8][PIT];

    int tid = threadIdx.x, lane = tid & 31, wid = tid >> 5;
    int wm = (wid >> 1) * 32, wn = (wid & 1) * 64;
    int fr = lane >> 2, kq = lane & 3;

    int a_row = tid & 127, a_kh = tid >> 7;
    const float* arow = g_h1 + (size_t)(r0 + a_row) * FF + a_kh * 8;
    int b_kp = tid >> 5, b_n = (tid & 31) * 4;
    const float* brow = wd + (size_t)e * FF * HH + n0 + b_n;

    float d[2][8][4];
#pragma unroll
    for (int i = 0; i < 2; i++)
#pragma unroll
        for (int j = 0; j < 8; j++)
#pragma unroll
            for (int k = 0; k < 4; k++) d[i][j][k] = 0.f;

#define G2_STS(st, A0, A1, B0, B1v) do {                                        \
    float af_[8] = {(A0).x,(A0).y,(A0).z,(A0).w,(A1).x,(A1).y,(A1).z,(A1).w};   \
    _Pragma("unroll")                                                           \
    for (int j_ = 0; j_ < 4; j_++)                                              \
        As[st][a_kh*4 + j_][a_row] = spb(af_[2*j_], af_[2*j_+1]);               \
    uint2 c0_ = spb((B0).x, (B1v).x);                                           \
    uint2 c1_ = spb((B0).y, (B1v).y);                                           \
    uint2 c2_ = spb((B0).z, (B1v).z);                                           \
    uint2 c3_ = spb((B0).w, (B1v).w);                                           \
    *(uint4*)&Bs[st][b_kp][b_n]     = make_uint4(c0_.x, c0_.y, c1_.x, c1_.y);   \
    *(uint4*)&Bs[st][b_kp][b_n + 2] = make_uint4(c2_.x, c2_.y, c3_.x, c3_.y);   \
} while (0)

    {
        float4 a0 = *(const float4*)(arow), a1 = *(const float4*)(arow + 4);
        size_t k0 = (size_t)(2*b_kp) * HH;
        float4 b0 = *(const float4*)(brow + k0), b1 = *(const float4*)(brow + k0 + HH);
        G2_STS(0, a0, a1, b0, b1);
    }
    float4 pa0 = *(const float4*)(arow + 16), pa1 = *(const float4*)(arow + 20);
    float4 pb0, pb1;
    {
        size_t k0 = (size_t)(16 + 2*b_kp) * HH;
        pb0 = *(const float4*)(brow + k0);  pb1 = *(const float4*)(brow + k0 + HH);
    }
    __syncthreads();

    const int chunks = FF / 16;   // 176
    for (int c = 0; c < chunks; c++) {
        int s = c & 1;
        if (c + 1 < chunks) {
            int s1 = s ^ 1;
            G2_STS(s1, pa0, pa1, pb0, pb1);
        }
        if (c + 2 < chunks) {
            pa0 = *(const float4*)(arow + (c+2)*16);
            pa1 = *(const float4*)(arow + (c+2)*16 + 4);
            size_t k0 = (size_t)((c+2)*16 + 2*b_kp) * HH;
            pb0 = *(const float4*)(brow + k0);
            pb1 = *(const float4*)(brow + k0 + HH);
        }
        uint32_t ahi[2][4], alo[2][4];
#pragma unroll
        for (int mt = 0; mt < 2; mt++) {
            int mb = wm + mt*16 + fr;
            uint2 q0 = As[s][kq][mb],   q1 = As[s][kq][mb+8];
            uint2 q2 = As[s][kq+4][mb], q3 = As[s][kq+4][mb+8];
            ahi[mt][0]=q0.x; ahi[mt][1]=q1.x; ahi[mt][2]=q2.x; ahi[mt][3]=q3.x;
            alo[mt][0]=q0.y; alo[mt][1]=q1.y; alo[mt][2]=q2.y; alo[mt][3]=q3.y;
        }
#pragma unroll
        for (int nt = 0; nt < 8; nt++) {
            int nn = wn + nt*8 + fr;
            uint2 b0 = Bs[s][kq][nn], b1 = Bs[s][kq+4][nn];
#pragma unroll
            for (int mt = 0; mt < 2; mt++) {
                mma_bf16(d[mt][nt], ahi[mt], b0.x, b1.x);
                mma_bf16(d[mt][nt], ahi[mt], b0.y, b1.y);
                mma_bf16(d[mt][nt], alo[mt], b0.x, b1.x);
            }
        }
        __syncthreads();
    }
#undef G2_STS

#pragma unroll
    for (int mt = 0; mt < 2; mt++) {
        int row = r0 + wm + mt*16 + fr;
#pragma unroll
        for (int nt = 0; nt < 8; nt++) {
            int col = n0 + wn + nt*8 + 2*kq;
            *(float2*)&g_y[(size_t)row * HH + col]       = make_float2(d[mt][nt][0], d[mt][nt][1]);
            *(float2*)&g_y[(size_t)(row + 8) * HH + col] = make_float2(d[mt][nt][2], d[mt][nt][3]);
        }
    }
}

__global__ void combine_kernel(float* __restrict__ out) {
    int i = blockIdx.x * blockDim.x + threadIdx.x;
    if (i >= TT * (HH/4)) return;
    int t = i / (HH/4);
    int c = (i - t * (HH/4)) * 4;
    int r0 = g_slot_row[2*t], r1 = g_slot_row[2*t+1];
    float w0 = g_tok_w[2*t], w1 = g_tok_w[2*t+1];
    float4 y0 = *(const float4*)(g_y + (size_t)r0 * HH + c);
    float4 y1 = *(const float4*)(g_y + (size_t)r1 * HH + c);
    float4 o;
    o.x = w0*y0.x + w1*y1.x;  o.y = w0*y0.y + w1*y1.y;
    o.z = w0*y0.z + w1*y1.z;  o.w = w0*y0.w + w1*y1.w;
    *(float4*)(out + (size_t)t * HH + c) = o;
}

extern "C" void kernel_launch(void* const* d_in, const int* in_sizes, int n_in,
                              void* d_out, int out_size) {
    const float* x  = (const float*)d_in[0];
    const float* rw = (const float*)d_in[1];
    const float* wg = (const float*)d_in[2];
    const float* wu = (const float*)d_in[3];
    const float* wd = (const float*)d_in[4];
    float* out = (float*)d_out;

    init_kernel<<<(PADMAX + 255) / 256, 256>>>();
    router_kernel<<<TT, 128>>>(x, rw);
    setup_kernel<<<1, 32>>>(out + (size_t)TT * HH);
    scatter_kernel<<<(SLOTS + 255) / 256, 256>>>();
    gemm1_kernel<<<dim3(RT_MAX, FF/64), 256>>>(x, wg, wu);
    gemm2_kernel<<<dim3(RT_MAX, HH/128), 256>>>(wd);
    combine_kernel<<<(TT * (HH/4) + 255) / 256, 256>>>(out);
}